// round 4
// baseline (speedup 1.0000x reference)
#include <cuda_runtime.h>

#define WDIM 1024
#define NPIX (WDIM * WDIM)
#define QTR (NPIX / 4)

static __device__ __forceinline__ unsigned long long pack2(float a, float b) {
    unsigned long long r;
    asm("mov.b64 %0, {%1,%2};" : "=l"(r) : "f"(a), "f"(b));
    return r;
}
static __device__ __forceinline__ void fma2(unsigned long long& d, unsigned long long a, unsigned long long b) {
    asm("fma.rn.f32x2 %0, %1, %2, %0;" : "+l"(d) : "l"(a), "l"(b));
}
static __device__ __forceinline__ float2 unpack2(unsigned long long v) {
    float2 r;
    asm("mov.b64 {%0,%1}, %2;" : "=f"(r.x), "=f"(r.y) : "l"(v));
    return r;
}

// softmax(9) + inverse rotation (register selects) + tanh + sigmoid.
// Executed by a 16-lane half-warp; stores are 64B-contiguous per plane.
static __device__ __forceinline__ void epilogue(const float* z, int d, int p,
                                                float* __restrict__ out)
{
    const int rb0 = d & 1;
    const int rb1 = (d >> 1) & 1;

    float mx = z[0];
#pragma unroll
    for (int j = 1; j < 9; j++) mx = fmaxf(mx, z[j]);
    float s[9];
    float sum = 0.0f;
#pragma unroll
    for (int j = 0; j < 9; j++) { s[j] = __expf(z[j] - mx); sum += s[j]; }
    float inv = __fdividef(1.0f, sum);

    const int I0[9] = {0,1,2,3,4,5,6,7,8};
    const int I1[9] = {2,5,8,1,4,7,0,3,6};
    const int I2[9] = {8,7,6,5,4,3,2,1,0};
    const int I3[9] = {6,3,0,7,4,1,8,5,2};
#pragma unroll
    for (int m = 0; m < 9; m++) {
        float v01 = rb0 ? s[I1[m]] : s[I0[m]];
        float v23 = rb0 ? s[I3[m]] : s[I2[m]];
        float v = rb1 ? v23 : v01;
        out[m * NPIX + p] = v * inv;
    }
    out[9 * NPIX + p] = tanhf(z[9]);
#pragma unroll
    for (int m = 0; m < 3; m++)
        out[(10 + m) * NPIX + p] = __fdividef(1.0f, 1.0f + __expf(-z[10 + m]));
}

__global__ void __launch_bounds__(128, 3) energy_cnn_kernel(
    const float* __restrict__ se, const float* __restrict__ te,
    const float* __restrict__ sr, const float* __restrict__ hc,
    const float* __restrict__ rot, const float* __restrict__ w1,
    const float* __restrict__ b1, const float* __restrict__ w2,
    const float* __restrict__ b2, float* __restrict__ out)
{
    // w1s[(c*9+j)*32 + o] = w1[o][c][j]   (w1 global layout: (32,6,3,3))
    __shared__ __align__(16) float w1s[54 * 32];
    // w2s[o*16 + m] = w2[m][o] (m<13), zero-padded rows of 16
    __shared__ __align__(16) float w2s[32 * 16];
    __shared__ __align__(16) unsigned long long b1p[16];
    __shared__ __align__(16) unsigned long long b2p[7];

    const int tid = threadIdx.x;
    for (int i = tid; i < 54 * 32; i += 128) {
        int cj = i >> 5, o = i & 31;
        w1s[i] = w1[o * 54 + cj];
    }
    for (int i = tid; i < 32 * 16; i += 128) {
        int o = i >> 4, m = i & 15;
        w2s[i] = (m < 13) ? w2[m * 32 + o] : 0.0f;
    }
    if (tid < 16) b1p[tid] = pack2(b1[2 * tid], b1[2 * tid + 1]);
    if (tid < 7) {
        float ba = b2[2 * tid];
        float bb = (2 * tid + 1 < 13) ? b2[2 * tid + 1] : 0.0f;
        b2p[tid] = pack2(ba, bb);
    }
    __syncthreads();

    // Lane pairing: lanes l and l^16 process the SAME 4 pixels;
    // half 0 computes output channels [0,16), half 1 [16,32).
    const int lane = tid & 31;
    const int half = lane >> 4;
    const int warp = tid >> 5;
    const int col  = blockIdx.x * 64 + warp * 16 + (lane & 15);  // pixel column in [0, QTR)
    const int x = col & (WDIM - 1);
    const int y = col >> 10;

    const float TP = 6.2831853071795864f;
    int d[4];
    int idx[4][9];
#pragma unroll
    for (int i = 0; i < 4; i++) {
        const int p = col + i * QTR;
        const int yi = y + i * (WDIM / 4);
        float t = rot[p] / TP * 4.0f;
        int di = ((int)t) & 3;
        d[i] = di;
        const int rb0 = di & 1, rb1 = (di >> 1) & 1;
#pragma unroll
        for (int j = 0; j < 9; j++) {
            const int dy0 = j / 3 - 1, dx0 = j % 3 - 1;
            int ay = rb1 ? -dy0 : dy0;
            int ax = rb1 ? -dx0 : dx0;
            int dy = rb0 ? -ax : ay;
            int dx = rb0 ? ay : ax;
            idx[i][j] = (((yi + dy) & (WDIM - 1)) << 10) + ((x + dx) & (WDIM - 1));
        }
    }

    // ---- layer 1: 54 -> 16 (this half's channels), 4 pixels share every weight load ----
    unsigned long long acc[4][8];
#pragma unroll
    for (int k = 0; k < 8; k++) {
        unsigned long long b = b1p[half * 8 + k];
#pragma unroll
        for (int i = 0; i < 4; i++) acc[i][k] = b;
    }

    const float* chans[6] = { se, te, sr, hc, hc + NPIX, hc + 2 * NPIX };
#pragma unroll
    for (int c = 0; c < 6; c++) {
        const float* __restrict__ ch = chans[c];
#pragma unroll
        for (int j = 0; j < 9; j++) {
            unsigned long long aa[4];
#pragma unroll
            for (int i = 0; i < 4; i++) {
                float a = __ldg(&ch[idx[i][j]]);
                aa[i] = pack2(a, a);
            }
            const ulonglong2* __restrict__ wrow =
                (const ulonglong2*)&w1s[(c * 9 + j) * 32 + half * 16];
#pragma unroll
            for (int k = 0; k < 4; k++) {
                ulonglong2 wv = wrow[k];
#pragma unroll
                for (int i = 0; i < 4; i++) {
                    fma2(acc[i][2 * k],     aa[i], wv.x);
                    fma2(acc[i][2 * k + 1], aa[i], wv.y);
                }
            }
        }
    }

    // ReLU -> h[i][oo], oo in [0,16) mapping to channel o = half*16+oo
    float h[4][16];
#pragma unroll
    for (int i = 0; i < 4; i++)
#pragma unroll
        for (int k = 0; k < 8; k++) {
            float2 v = unpack2(acc[i][k]);
            h[i][2 * k]     = fmaxf(v.x, 0.0f);
            h[i][2 * k + 1] = fmaxf(v.y, 0.0f);
        }

    // ---- layer 2 partials: this half's 16 input channels -> 13 outputs (7 pairs) ----
    unsigned long long x2[4][7];
#pragma unroll
    for (int m = 0; m < 7; m++) {
        unsigned long long b = half ? 0ULL : b2p[m];   // bias added by half 0 only
#pragma unroll
        for (int i = 0; i < 4; i++) x2[i][m] = b;
    }
#pragma unroll
    for (int oo = 0; oo < 16; oo++) {
        const int o = half * 16 + oo;
        const ulonglong2* __restrict__ wq = (const ulonglong2*)&w2s[o * 16];
        ulonglong2 wv0 = wq[0];
        ulonglong2 wv1 = wq[1];
        ulonglong2 wv2 = wq[2];
        ulonglong2 wv3 = wq[3];
#pragma unroll
        for (int i = 0; i < 4; i++) {
            unsigned long long hh = pack2(h[i][oo], h[i][oo]);
            fma2(x2[i][0], hh, wv0.x);
            fma2(x2[i][1], hh, wv0.y);
            fma2(x2[i][2], hh, wv1.x);
            fma2(x2[i][3], hh, wv1.y);
            fma2(x2[i][4], hh, wv2.x);
            fma2(x2[i][5], hh, wv2.y);
            fma2(x2[i][6], hh, wv3.x);
        }
    }

    // ---- cross-half reduction (shfl.xor 16) + epilogue (2 pixels per half) ----
#pragma unroll
    for (int i = 0; i < 4; i++) {
        float z[13];
#pragma unroll
        for (int m = 0; m < 6; m++) {
            float2 v = unpack2(x2[i][m]);
            v.x += __shfl_xor_sync(0xffffffffu, v.x, 16);
            v.y += __shfl_xor_sync(0xffffffffu, v.y, 16);
            z[2 * m] = v.x; z[2 * m + 1] = v.y;
        }
        {
            float v = unpack2(x2[i][6]).x;
            v += __shfl_xor_sync(0xffffffffu, v, 16);
            z[12] = v;
        }
        if ((i >> 1) == half)
            epilogue(z, d[i], col + i * QTR, out);
    }
}

extern "C" void kernel_launch(void* const* d_in, const int* in_sizes, int n_in,
                              void* d_out, int out_size)
{
    const float* se  = (const float*)d_in[0];
    const float* te  = (const float*)d_in[1];
    const float* sr  = (const float*)d_in[2];
    const float* hc  = (const float*)d_in[3];
    const float* rot = (const float*)d_in[4];
    const float* w1  = (const float*)d_in[5];
    const float* b1  = (const float*)d_in[6];
    const float* w2  = (const float*)d_in[7];
    const float* b2  = (const float*)d_in[8];
    float* out = (float*)d_out;

    energy_cnn_kernel<<<QTR / 64, 128>>>(se, te, sr, hc, rot, w1, b1, w2, b2, out);
}

// round 5
// speedup vs baseline: 1.0002x; 1.0002x over previous
#include <cuda_runtime.h>

#define WDIM 1024
#define NPIX (WDIM * WDIM)
#define QTR (NPIX / 4)

static __device__ __forceinline__ unsigned long long pack2(float a, float b) {
    unsigned long long r;
    asm("mov.b64 %0, {%1,%2};" : "=l"(r) : "f"(a), "f"(b));
    return r;
}
static __device__ __forceinline__ void fma2(unsigned long long& d, unsigned long long a, unsigned long long b) {
    asm("fma.rn.f32x2 %0, %1, %2, %0;" : "+l"(d) : "l"(a), "l"(b));
}
static __device__ __forceinline__ float2 unpack2(unsigned long long v) {
    float2 r;
    asm("mov.b64 {%0,%1}, %2;" : "=f"(r.x), "=f"(r.y) : "l"(v));
    return r;
}

// softmax(9) + inverse rotation (register selects) + tanh + sigmoid.
// Executed by a 16-lane half-warp; stores are 64B-contiguous per plane.
static __device__ __forceinline__ void epilogue(const float* z, int d, int p,
                                                float* __restrict__ out)
{
    const int rb0 = d & 1;
    const int rb1 = (d >> 1) & 1;

    float mx = z[0];
#pragma unroll
    for (int j = 1; j < 9; j++) mx = fmaxf(mx, z[j]);
    float s[9];
    float sum = 0.0f;
#pragma unroll
    for (int j = 0; j < 9; j++) { s[j] = __expf(z[j] - mx); sum += s[j]; }
    float inv = __fdividef(1.0f, sum);

    const int I0[9] = {0,1,2,3,4,5,6,7,8};
    const int I1[9] = {2,5,8,1,4,7,0,3,6};
    const int I2[9] = {8,7,6,5,4,3,2,1,0};
    const int I3[9] = {6,3,0,7,4,1,8,5,2};
#pragma unroll
    for (int m = 0; m < 9; m++) {
        float v01 = rb0 ? s[I1[m]] : s[I0[m]];
        float v23 = rb0 ? s[I3[m]] : s[I2[m]];
        float v = rb1 ? v23 : v01;
        out[m * NPIX + p] = v * inv;
    }
    out[9 * NPIX + p] = tanhf(z[9]);
#pragma unroll
    for (int m = 0; m < 3; m++)
        out[(10 + m) * NPIX + p] = __fdividef(1.0f, 1.0f + __expf(-z[10 + m]));
}

__global__ void __launch_bounds__(128, 3) energy_cnn_kernel(
    const float* __restrict__ se, const float* __restrict__ te,
    const float* __restrict__ sr, const float* __restrict__ hc,
    const float* __restrict__ rot, const float* __restrict__ w1,
    const float* __restrict__ b1, const float* __restrict__ w2,
    const float* __restrict__ b2, float* __restrict__ out)
{
    // w1s[(c*9+j)*32 + o] = w1[o][c][j]   (w1 global layout: (32,6,3,3))
    __shared__ __align__(16) float w1s[54 * 32];
    // w2s[o*16 + m] = w2[m][o] (m<13), zero-padded rows of 16
    __shared__ __align__(16) float w2s[32 * 16];
    __shared__ __align__(16) unsigned long long b1p[16];
    __shared__ __align__(16) unsigned long long b2p[7];

    const int tid = threadIdx.x;
    for (int i = tid; i < 54 * 32; i += 128) {
        int cj = i >> 5, o = i & 31;
        w1s[i] = w1[o * 54 + cj];
    }
    for (int i = tid; i < 32 * 16; i += 128) {
        int o = i >> 4, m = i & 15;
        w2s[i] = (m < 13) ? w2[m * 32 + o] : 0.0f;
    }
    if (tid < 16) b1p[tid] = pack2(b1[2 * tid], b1[2 * tid + 1]);
    if (tid < 7) {
        float ba = b2[2 * tid];
        float bb = (2 * tid + 1 < 13) ? b2[2 * tid + 1] : 0.0f;
        b2p[tid] = pack2(ba, bb);
    }
    __syncthreads();

    // Lane pairing: lanes l and l^16 process the SAME 4 pixels;
    // half 0 computes output channels [0,16), half 1 [16,32).
    const int lane = tid & 31;
    const int half = lane >> 4;
    const int warp = tid >> 5;
    const int col  = blockIdx.x * 64 + warp * 16 + (lane & 15);  // pixel column in [0, QTR)
    const int x = col & (WDIM - 1);
    const int y = col >> 10;

    const float TP = 6.2831853071795864f;
    int d[4];
    int idx[4][9];
#pragma unroll
    for (int i = 0; i < 4; i++) {
        const int p = col + i * QTR;
        const int yi = y + i * (WDIM / 4);
        float t = rot[p] / TP * 4.0f;
        int di = ((int)t) & 3;
        d[i] = di;
        const int rb0 = di & 1, rb1 = (di >> 1) & 1;
#pragma unroll
        for (int j = 0; j < 9; j++) {
            const int dy0 = j / 3 - 1, dx0 = j % 3 - 1;
            int ay = rb1 ? -dy0 : dy0;
            int ax = rb1 ? -dx0 : dx0;
            int dy = rb0 ? -ax : ay;
            int dx = rb0 ? ay : ax;
            idx[i][j] = (((yi + dy) & (WDIM - 1)) << 10) + ((x + dx) & (WDIM - 1));
        }
    }

    // ---- layer 1: 54 -> 16 (this half's channels), 4 pixels share every weight load ----
    unsigned long long acc[4][8];
#pragma unroll
    for (int k = 0; k < 8; k++) {
        unsigned long long b = b1p[half * 8 + k];
#pragma unroll
        for (int i = 0; i < 4; i++) acc[i][k] = b;
    }

    const float* chans[6] = { se, te, sr, hc, hc + NPIX, hc + 2 * NPIX };
#pragma unroll
    for (int c = 0; c < 6; c++) {
        const float* __restrict__ ch = chans[c];
#pragma unroll
        for (int j = 0; j < 9; j++) {
            unsigned long long aa[4];
#pragma unroll
            for (int i = 0; i < 4; i++) {
                float a = __ldg(&ch[idx[i][j]]);
                aa[i] = pack2(a, a);
            }
            const ulonglong2* __restrict__ wrow =
                (const ulonglong2*)&w1s[(c * 9 + j) * 32 + half * 16];
#pragma unroll
            for (int k = 0; k < 4; k++) {
                ulonglong2 wv = wrow[k];
#pragma unroll
                for (int i = 0; i < 4; i++) {
                    fma2(acc[i][2 * k],     aa[i], wv.x);
                    fma2(acc[i][2 * k + 1], aa[i], wv.y);
                }
            }
        }
    }

    // ReLU -> h[i][oo], oo in [0,16) mapping to channel o = half*16+oo
    float h[4][16];
#pragma unroll
    for (int i = 0; i < 4; i++)
#pragma unroll
        for (int k = 0; k < 8; k++) {
            float2 v = unpack2(acc[i][k]);
            h[i][2 * k]     = fmaxf(v.x, 0.0f);
            h[i][2 * k + 1] = fmaxf(v.y, 0.0f);
        }

    // ---- layer 2 partials: this half's 16 input channels -> 13 outputs (7 pairs) ----
    unsigned long long x2[4][7];
#pragma unroll
    for (int m = 0; m < 7; m++) {
        unsigned long long b = half ? 0ULL : b2p[m];   // bias added by half 0 only
#pragma unroll
        for (int i = 0; i < 4; i++) x2[i][m] = b;
    }
#pragma unroll
    for (int oo = 0; oo < 16; oo++) {
        const int o = half * 16 + oo;
        const ulonglong2* __restrict__ wq = (const ulonglong2*)&w2s[o * 16];
        ulonglong2 wv0 = wq[0];
        ulonglong2 wv1 = wq[1];
        ulonglong2 wv2 = wq[2];
        ulonglong2 wv3 = wq[3];
#pragma unroll
        for (int i = 0; i < 4; i++) {
            unsigned long long hh = pack2(h[i][oo], h[i][oo]);
            fma2(x2[i][0], hh, wv0.x);
            fma2(x2[i][1], hh, wv0.y);
            fma2(x2[i][2], hh, wv1.x);
            fma2(x2[i][3], hh, wv1.y);
            fma2(x2[i][4], hh, wv2.x);
            fma2(x2[i][5], hh, wv2.y);
            fma2(x2[i][6], hh, wv3.x);
        }
    }

    // ---- cross-half reduction (shfl.xor 16) + epilogue (2 pixels per half) ----
#pragma unroll
    for (int i = 0; i < 4; i++) {
        float z[13];
#pragma unroll
        for (int m = 0; m < 6; m++) {
            float2 v = unpack2(x2[i][m]);
            v.x += __shfl_xor_sync(0xffffffffu, v.x, 16);
            v.y += __shfl_xor_sync(0xffffffffu, v.y, 16);
            z[2 * m] = v.x; z[2 * m + 1] = v.y;
        }
        {
            float v = unpack2(x2[i][6]).x;
            v += __shfl_xor_sync(0xffffffffu, v, 16);
            z[12] = v;
        }
        if ((i >> 1) == half)
            epilogue(z, d[i], col + i * QTR, out);
    }
}

extern "C" void kernel_launch(void* const* d_in, const int* in_sizes, int n_in,
                              void* d_out, int out_size)
{
    const float* se  = (const float*)d_in[0];
    const float* te  = (const float*)d_in[1];
    const float* sr  = (const float*)d_in[2];
    const float* hc  = (const float*)d_in[3];
    const float* rot = (const float*)d_in[4];
    const float* w1  = (const float*)d_in[5];
    const float* b1  = (const float*)d_in[6];
    const float* w2  = (const float*)d_in[7];
    const float* b2  = (const float*)d_in[8];
    float* out = (float*)d_out;

    energy_cnn_kernel<<<QTR / 64, 128>>>(se, te, sr, hc, rot, w1, b1, w2, b2, out);
}

// round 6
// speedup vs baseline: 1.3825x; 1.3821x over previous
#include <cuda_runtime.h>
#include <cstdint>

#define WDIM 1024
#define NPIX (WDIM * WDIM)
#define HALF (NPIX / 2)

// ---- constant-bank weight storage (written by prep kernel each graph replay) ----
// CW1[(c*9+j)*8 + k] : 16B = 4 floats = w1t[(c*9+j)*32 + 4k .. 4k+3]  (w1t[cj][o] = w1[o][cj])
// CW2[o*4 + m]       : 16B = 4 floats = w2t[o*16 + 4m .. 4m+3]        (w2t[o][m] = w2[m][o], m>=13 -> 0)
// CB1[i]             : packed pair {b1[2i], b1[2i+1]}
// CB2[m]             : packed pair {b2[2m], b2[2m+1]} (pad 0 beyond 13)
__constant__ __align__(16) ulonglong2 CW1[54 * 8];
__constant__ __align__(16) ulonglong2 CW2[32 * 4];
__constant__ __align__(16) unsigned long long CB1[16];
__constant__ __align__(16) unsigned long long CB2[7];

static __device__ __forceinline__ unsigned long long pack2(float a, float b) {
    unsigned long long r;
    asm("mov.b64 %0, {%1,%2};" : "=l"(r) : "f"(a), "f"(b));
    return r;
}
static __device__ __forceinline__ void fma2(unsigned long long& d, unsigned long long a, unsigned long long b) {
    asm("fma.rn.f32x2 %0, %1, %2, %0;" : "+l"(d) : "l"(a), "l"(b));
}
static __device__ __forceinline__ float2 unpack2(unsigned long long v) {
    float2 r;
    asm("mov.b64 {%0,%1}, %2;" : "=f"(r.x), "=f"(r.y) : "l"(v));
    return r;
}

// Prep: transpose/pack weights into the constant bank (via its global-memory alias).
__global__ void prep_kernel(const float* __restrict__ w1, const float* __restrict__ b1,
                            const float* __restrict__ w2, const float* __restrict__ b2,
                            float* __restrict__ cw1, float* __restrict__ cw2,
                            float* __restrict__ cb1, float* __restrict__ cb2)
{
    const int tid = threadIdx.x;
    for (int i = tid; i < 54 * 32; i += 256) {
        int cj = i >> 5, o = i & 31;
        cw1[i] = w1[o * 54 + cj];
    }
    for (int i = tid; i < 32 * 16; i += 256) {
        int o = i >> 4, m = i & 15;
        cw2[i] = (m < 13) ? w2[m * 32 + o] : 0.0f;
    }
    if (tid < 32) cb1[tid] = b1[tid];
    if (tid < 14) cb2[tid] = (tid < 13) ? b2[tid] : 0.0f;
}

// softmax(9) + inverse rotation (register selects) + tanh + sigmoid; coalesced stores.
static __device__ __forceinline__ void epilogue(const float* z, int d, int p,
                                                float* __restrict__ out)
{
    const int rb0 = d & 1;
    const int rb1 = (d >> 1) & 1;

    float mx = z[0];
#pragma unroll
    for (int j = 1; j < 9; j++) mx = fmaxf(mx, z[j]);
    float s[9];
    float sum = 0.0f;
#pragma unroll
    for (int j = 0; j < 9; j++) { s[j] = __expf(z[j] - mx); sum += s[j]; }
    float inv = __fdividef(1.0f, sum);

    const int I0[9] = {0,1,2,3,4,5,6,7,8};
    const int I1[9] = {2,5,8,1,4,7,0,3,6};
    const int I2[9] = {8,7,6,5,4,3,2,1,0};
    const int I3[9] = {6,3,0,7,4,1,8,5,2};
#pragma unroll
    for (int m = 0; m < 9; m++) {
        float v01 = rb0 ? s[I1[m]] : s[I0[m]];
        float v23 = rb0 ? s[I3[m]] : s[I2[m]];
        float v = rb1 ? v23 : v01;
        out[m * NPIX + p] = v * inv;
    }
    out[9 * NPIX + p] = tanhf(z[9]);
#pragma unroll
    for (int m = 0; m < 3; m++)
        out[(10 + m) * NPIX + p] = __fdividef(1.0f, 1.0f + __expf(-z[10 + m]));
}

__global__ void __launch_bounds__(256, 2) energy_cnn_kernel(
    const float* __restrict__ se, const float* __restrict__ te,
    const float* __restrict__ sr, const float* __restrict__ hc,
    const float* __restrict__ rot, float* __restrict__ out)
{
    const int tid = threadIdx.x;

    // Two pixels per thread: p0 in the top half, p1 = p0 + HALF.
    const int p0 = blockIdx.x * 256 + tid;
    const int p1 = p0 + HALF;
    const int x0 = p0 & (WDIM - 1), y0 = p0 >> 10;
    const int x1 = x0,              y1 = y0 + (WDIM / 2);

    const float TP = 6.2831853071795864f;
    int d0, d1;
    {
        float t = rot[p0] / TP * 4.0f;  d0 = ((int)t) & 3;
        float u = rot[p1] / TP * 4.0f;  d1 = ((int)u) & 3;
    }

    // Rotated gather addresses (rotation = address permutation).
    int idx0[9], idx1[9];
    {
        const int rb00 = d0 & 1, rb01 = (d0 >> 1) & 1;
        const int rb10 = d1 & 1, rb11 = (d1 >> 1) & 1;
#pragma unroll
        for (int j = 0; j < 9; j++) {
            const int dy0 = j / 3 - 1, dx0 = j % 3 - 1;
            {
                int ay = rb01 ? -dy0 : dy0;
                int ax = rb01 ? -dx0 : dx0;
                int dy = rb00 ? -ax : ay;
                int dx = rb00 ? ay : ax;
                idx0[j] = (((y0 + dy) & (WDIM - 1)) << 10) + ((x0 + dx) & (WDIM - 1));
            }
            {
                int ay = rb11 ? -dy0 : dy0;
                int ax = rb11 ? -dx0 : dx0;
                int dy = rb10 ? -ax : ay;
                int dx = rb10 ? ay : ax;
                idx1[j] = (((y1 + dy) & (WDIM - 1)) << 10) + ((x1 + dx) & (WDIM - 1));
            }
        }
    }

    // ---- layer 1: 54 -> 32, output-pair packed; weights via constant port ----
    unsigned long long acc0[16], acc1[16];
#pragma unroll
    for (int i = 0; i < 16; i++) {
        unsigned long long b = CB1[i];
        acc0[i] = b; acc1[i] = b;
    }

    const float* chans[6] = { se, te, sr, hc, hc + NPIX, hc + 2 * NPIX };
#pragma unroll
    for (int c = 0; c < 6; c++) {
        const float* __restrict__ ch = chans[c];
#pragma unroll
        for (int j = 0; j < 9; j++) {
            float a0 = __ldg(&ch[idx0[j]]);
            float a1 = __ldg(&ch[idx1[j]]);
            unsigned long long aa0 = pack2(a0, a0);
            unsigned long long aa1 = pack2(a1, a1);
#pragma unroll
            for (int i = 0; i < 8; i++) {
                ulonglong2 wv = CW1[(c * 9 + j) * 8 + i];   // LDC.128, constant port
                fma2(acc0[2 * i],     aa0, wv.x);
                fma2(acc0[2 * i + 1], aa0, wv.y);
                fma2(acc1[2 * i],     aa1, wv.x);
                fma2(acc1[2 * i + 1], aa1, wv.y);
            }
        }
    }

    float h0[32], h1[32];
#pragma unroll
    for (int i = 0; i < 16; i++) {
        float2 v0 = unpack2(acc0[i]);
        float2 v1 = unpack2(acc1[i]);
        h0[2 * i]     = fmaxf(v0.x, 0.0f);
        h0[2 * i + 1] = fmaxf(v0.y, 0.0f);
        h1[2 * i]     = fmaxf(v1.x, 0.0f);
        h1[2 * i + 1] = fmaxf(v1.y, 0.0f);
    }

    // ---- layer 2: 32 -> 13 (7 output pairs); weights via constant port ----
    unsigned long long x20[7], x21[7];
#pragma unroll
    for (int m = 0; m < 7; m++) {
        unsigned long long b = CB2[m];
        x20[m] = b; x21[m] = b;
    }
#pragma unroll
    for (int o = 0; o < 32; o++) {
        unsigned long long hh0 = pack2(h0[o], h0[o]);
        unsigned long long hh1 = pack2(h1[o], h1[o]);
        ulonglong2 wv0 = CW2[o * 4 + 0];
        ulonglong2 wv1 = CW2[o * 4 + 1];
        ulonglong2 wv2 = CW2[o * 4 + 2];
        ulonglong2 wv3 = CW2[o * 4 + 3];
        fma2(x20[0], hh0, wv0.x);  fma2(x21[0], hh1, wv0.x);
        fma2(x20[1], hh0, wv0.y);  fma2(x21[1], hh1, wv0.y);
        fma2(x20[2], hh0, wv1.x);  fma2(x21[2], hh1, wv1.x);
        fma2(x20[3], hh0, wv1.y);  fma2(x21[3], hh1, wv1.y);
        fma2(x20[4], hh0, wv2.x);  fma2(x21[4], hh1, wv2.x);
        fma2(x20[5], hh0, wv2.y);  fma2(x21[5], hh1, wv2.y);
        fma2(x20[6], hh0, wv3.x);  fma2(x21[6], hh1, wv3.x);
    }

    float z0[13], z1[13];
#pragma unroll
    for (int m = 0; m < 6; m++) {
        float2 v0 = unpack2(x20[m]);
        float2 v1 = unpack2(x21[m]);
        z0[2 * m] = v0.x; z0[2 * m + 1] = v0.y;
        z1[2 * m] = v1.x; z1[2 * m + 1] = v1.y;
    }
    z0[12] = unpack2(x20[6]).x;
    z1[12] = unpack2(x21[6]).x;

    epilogue(z0, d0, p0, out);
    epilogue(z1, d1, p1, out);
}

extern "C" void kernel_launch(void* const* d_in, const int* in_sizes, int n_in,
                              void* d_out, int out_size)
{
    const float* se  = (const float*)d_in[0];
    const float* te  = (const float*)d_in[1];
    const float* sr  = (const float*)d_in[2];
    const float* hc  = (const float*)d_in[3];
    const float* rot = (const float*)d_in[4];
    const float* w1  = (const float*)d_in[5];
    const float* b1  = (const float*)d_in[6];
    const float* w2  = (const float*)d_in[7];
    const float* b2  = (const float*)d_in[8];
    float* out = (float*)d_out;

    void *cw1p, *cw2p, *cb1p, *cb2p;
    cudaGetSymbolAddress(&cw1p, CW1);
    cudaGetSymbolAddress(&cw2p, CW2);
    cudaGetSymbolAddress(&cb1p, CB1);
    cudaGetSymbolAddress(&cb2p, CB2);

    prep_kernel<<<1, 256>>>(w1, b1, w2, b2,
                            (float*)cw1p, (float*)cw2p, (float*)cb1p, (float*)cb2p);
    energy_cnn_kernel<<<HALF / 256, 256>>>(se, te, sr, hc, rot, out);
}